// round 2
// baseline (speedup 1.0000x reference)
#include <cuda_runtime.h>
#include <cuda_bf16.h>

// ---------------------------------------------------------------------------
// ResidualVectorQuantize (eval mode), fp32 faithful.
// B=16, T=4096, D=512, N=9, K=1024, d=8.
// Output layout (float32): [z_q (B*T*D)] [codes (B*T*N)] [latents (B*T*N*d)]
//                          [commitment_loss] [codebook_loss]
// ---------------------------------------------------------------------------

#define BT   65536
#define DDIM 512
#define DLAT 8
#define KCB  1024
#define NCB  9

#define OFF_CODES 33554432ull
#define OFF_LAT   34144256ull
#define OFF_LOSS  38862848ull

#define TPB_TOKENS 32          // tokens per block (2 per warp)
#define THREADS    512
#define NBLOCKS    (BT / TPB_TOKENS)   // 2048

// dynamic smem layout sizes (bytes): see partition below
#define SMEM_BYTES 76832

// -------------------------- device scratch --------------------------------
__device__ double g_loss;
__device__ float4 g_Win4 [NCB * 1024];   // [i][dim][c] as 2x float4 per dim
__device__ float4 g_Wout4[NCB * 1024];   // [i][dim][c] as 2x float4 per dim
__device__ float4 g_Cbn4 [NCB * 2048];   // [i][k][c]   as 2x float4 per k
__device__ float  g_Cbs  [NCB * KCB];    // sum(cb_n^2) per codeword

// monotone float -> sortable uint
__device__ __forceinline__ unsigned f2s(float f) {
    unsigned u = __float_as_uint(f);
    return (u & 0x80000000u) ? ~u : (u | 0x80000000u);
}

__device__ __forceinline__ unsigned long long umin64(unsigned long long a,
                                                     unsigned long long b) {
    return a < b ? a : b;
}

// -------------------------- precompute kernel -----------------------------
// 9 blocks (one per codebook), 512 threads.
__global__ void rvq_pre(const float* __restrict__ in_v,
                        const float* __restrict__ in_g,
                        const float* __restrict__ out_v,
                        const float* __restrict__ out_g,
                        const float* __restrict__ cb) {
    const int i = blockIdx.x;
    const int tid = threadIdx.x;
    const int warp = tid >> 5, lane = tid & 31;
    __shared__ float nIn[8];

    // ---- in_proj column norms over D (per c) ----
    if (warp < 8) {
        float s = 0.f;
        #pragma unroll
        for (int j = 0; j < 16; j++) {
            float v = in_v[i * 4096 + (lane + 32 * j) * 8 + warp];
            s += v * v;
        }
        #pragma unroll
        for (int off = 16; off >= 1; off >>= 1)
            s += __shfl_xor_sync(0xffffffffu, s, off);
        if (lane == 0) nIn[warp] = s;
    }
    __syncthreads();

    // W_in = g * v / max(||v||, eps), layout [dim][c]
    for (int idx = tid; idx < 4096; idx += THREADS) {
        int c = idx & 7;
        float den = fmaxf(sqrtf(nIn[c]), 1e-12f);
        ((float*)g_Win4)[i * 4096 + idx] = in_g[i * 8 + c] * in_v[i * 4096 + idx] / den;
    }

    // ---- out_proj: norm over d (axis 0 of (d,D)) per output dim ----
    {
        int dim = tid;  // 0..511
        float vv[8];
        float s = 0.f;
        #pragma unroll
        for (int c = 0; c < 8; c++) {
            vv[c] = out_v[i * 4096 + c * 512 + dim];
            s += vv[c] * vv[c];
        }
        float den = fmaxf(sqrtf(s), 1e-12f);
        float g = out_g[i * 512 + dim];
        #pragma unroll
        for (int c = 0; c < 8; c++)
            ((float*)g_Wout4)[i * 4096 + dim * 8 + c] = g * vv[c] / den;
    }

    // ---- codebook: cb_n = cb / max(||cb||, eps); cbs = sum(cb_n^2) ----
    for (int k = tid; k < KCB; k += THREADS) {
        float vv[8];
        float s = 0.f;
        #pragma unroll
        for (int c = 0; c < 8; c++) {
            vv[c] = cb[(size_t)i * 8192 + k * 8 + c];
            s += vv[c] * vv[c];
        }
        float den = fmaxf(sqrtf(s), 1e-12f);
        float ss = 0.f;
        #pragma unroll
        for (int c = 0; c < 8; c++) {
            float cn = vv[c] / den;
            ((float*)g_Cbn4)[(size_t)i * 8192 + k * 8 + c] = cn;
            ss += cn * cn;
        }
        g_Cbs[i * KCB + k] = ss;
    }
}

__global__ void rvq_zero() { g_loss = 0.0; }

__global__ void rvq_fin(float* __restrict__ out) {
    // total_sum / (B*T*d) = / 524288 ; commit == cbloss numerically
    float L = (float)(g_loss * (1.0 / 524288.0));
    out[OFF_LOSS]     = L;
    out[OFF_LOSS + 1] = L;
}

// ----------------------------- main kernel --------------------------------
__global__ __launch_bounds__(THREADS, 1)
void rvq_main(const float* __restrict__ z,
              const float* __restrict__ in_b,
              const float* __restrict__ out_b,
              const float* __restrict__ codebooks,
              float* __restrict__ out) {
    extern __shared__ char smem_raw[];
    float4* sWin4  = (float4*)smem_raw;                  // 1024 -> 16384 B
    float4* sWout4 = sWin4 + 1024;                       // 1024 -> 16384 B
    float4* sCb4   = sWout4 + 1024;                      // 2048 -> 32768 B
    float*  sCbs   = (float*)(sCb4 + 2048);              // 1024 ->  4096 B
    float*  sOutB  = sCbs + 1024;                        //  512 ->  2048 B
    float*  sInB   = sOutB + 512;                        //    8 ->    32 B
    float*  sZe    = sInB + 8;                           //  256 ->  1024 B
    float*  sEnc   = sZe + 256;                          //  256 ->  1024 B
    float*  sZq    = sEnc + 256;                         //  256 ->  1024 B
    unsigned long long* sCand = (unsigned long long*)(sZq + 256); // 256 -> 2048 B

    const int tid  = threadIdx.x;
    const int warp = tid >> 5;
    const int lane = tid & 31;
    const int tokBase = blockIdx.x * TPB_TOKENS;
    const int t0g = tokBase + warp * 2;    // this warp's first global token

    // residual in registers: lane owns dims lane + 32*j (coalesced)
    float res0[16], res1[16];
    #pragma unroll
    for (int j = 0; j < 16; j++) {
        res0[j] = z[(size_t)t0g * DDIM + lane + 32 * j];
        res1[j] = z[(size_t)(t0g + 1) * DDIM + lane + 32 * j];
    }
    float lossAcc = 0.f;   // only threads 0..31 accumulate

    for (int i = 0; i < NCB; i++) {
        __syncthreads();   // previous iter's smem consumers done
        // ---- stage weights for this codebook ----
        {
            const float4* pw = g_Win4  + i * 1024;
            const float4* po = g_Wout4 + i * 1024;
            const float4* pc = g_Cbn4  + i * 2048;
            #pragma unroll
            for (int idx = tid; idx < 1024; idx += THREADS) {
                sWin4[idx]  = pw[idx];
                sWout4[idx] = po[idx];
                sCbs[idx]   = g_Cbs[i * KCB + idx];
            }
            #pragma unroll
            for (int idx = tid; idx < 2048; idx += THREADS)
                sCb4[idx] = pc[idx];
            sOutB[tid & 511] = out_b[i * 512 + (tid & 511)];
            if (tid < 8) sInB[tid] = in_b[i * 8 + tid];
        }
        __syncthreads();

        // ---- in_proj: z_e = residual @ W_in + b  (per warp, 2 tokens) ----
        {
            float acc[16];
            #pragma unroll
            for (int q = 0; q < 16; q++) acc[q] = 0.f;
            #pragma unroll
            for (int j = 0; j < 16; j++) {
                int dim = lane + 32 * j;
                float4 wa = sWin4[2 * dim], wb = sWin4[2 * dim + 1];
                float r0 = res0[j], r1 = res1[j];
                acc[0] = fmaf(r0, wa.x, acc[0]); acc[1] = fmaf(r0, wa.y, acc[1]);
                acc[2] = fmaf(r0, wa.z, acc[2]); acc[3] = fmaf(r0, wa.w, acc[3]);
                acc[4] = fmaf(r0, wb.x, acc[4]); acc[5] = fmaf(r0, wb.y, acc[5]);
                acc[6] = fmaf(r0, wb.z, acc[6]); acc[7] = fmaf(r0, wb.w, acc[7]);
                acc[8]  = fmaf(r1, wa.x, acc[8]);  acc[9]  = fmaf(r1, wa.y, acc[9]);
                acc[10] = fmaf(r1, wa.z, acc[10]); acc[11] = fmaf(r1, wa.w, acc[11]);
                acc[12] = fmaf(r1, wb.x, acc[12]); acc[13] = fmaf(r1, wb.y, acc[13]);
                acc[14] = fmaf(r1, wb.z, acc[14]); acc[15] = fmaf(r1, wb.w, acc[15]);
            }
            #pragma unroll
            for (int off = 16; off >= 1; off >>= 1) {
                #pragma unroll
                for (int q = 0; q < 16; q++)
                    acc[q] += __shfl_xor_sync(0xffffffffu, acc[q], off);
            }
            // lanes 0..15: (t = lane>>3, c = lane&7)
            int c = lane & 7;
            int tsel = (lane >> 3) & 1;
            float ze = acc[tsel * 8 + c] + sInB[c];
            float s = ze * ze;
            s += __shfl_xor_sync(0xffffffffu, s, 4);
            s += __shfl_xor_sync(0xffffffffu, s, 2);
            s += __shfl_xor_sync(0xffffffffu, s, 1);
            float enc = ze / fmaxf(sqrtf(s), 1e-12f);
            if (lane < 16) {
                int tl = warp * 2 + tsel;
                sZe[tl * 8 + c]  = ze;
                sEnc[tl * 8 + c] = enc;
                out[OFF_LAT + (size_t)(tokBase + tl) * 72 + i * 8 + c] = ze;
            }
        }
        __syncthreads();

        // ---- NN search: register-resident codebook (4 cw / thread) ----
        {
            int grp = warp >> 3;                 // warps 0-7 -> tokens 0-15
            int cwBase = (tid & 255) * 4;        // this thread's 4 codewords
            float4 ca[4], cbv[4];
            float  cs[4];
            #pragma unroll
            for (int q = 0; q < 4; q++) {
                ca[q]  = sCb4[(cwBase + q) * 2];
                cbv[q] = sCb4[(cwBase + q) * 2 + 1];
                cs[q]  = sCbs[cwBase + q];
            }
            #pragma unroll 4
            for (int tt = 0; tt < 16; tt++) {
                int t = grp * 16 + tt;
                float4 ea = *(const float4*)&sEnc[t * 8];
                float4 eb = *(const float4*)&sEnc[t * 8 + 4];
                unsigned long long best = ~0ull;
                #pragma unroll
                for (int q = 0; q < 4; q++) {
                    float dot;
                    dot = ea.x * ca[q].x;
                    dot = fmaf(ea.y, ca[q].y, dot);
                    dot = fmaf(ea.z, ca[q].z, dot);
                    dot = fmaf(ea.w, ca[q].w, dot);
                    dot = fmaf(eb.x, cbv[q].x, dot);
                    dot = fmaf(eb.y, cbv[q].y, dot);
                    dot = fmaf(eb.z, cbv[q].z, dot);
                    dot = fmaf(eb.w, cbv[q].w, dot);
                    float dist = fmaf(-2.f, dot, cs[q]);
                    unsigned long long key =
                        ((unsigned long long)f2s(dist) << 32) |
                        (unsigned)(cwBase + q);
                    best = umin64(best, key);
                }
                #pragma unroll
                for (int off = 16; off >= 1; off >>= 1)
                    best = umin64(best, __shfl_xor_sync(0xffffffffu, best, off));
                if (lane == 0) sCand[t * 8 + (warp & 7)] = best;
            }
        }
        __syncthreads();

        // ---- finalize per token: codes, gather raw cw, z_q_st, loss ----
        if (tid < TPB_TOKENS) {
            int t = tid;
            unsigned long long best = sCand[t * 8];
            #pragma unroll
            for (int w = 1; w < 8; w++) best = umin64(best, sCand[t * 8 + w]);
            unsigned k = (unsigned)(best & 0xffffffffu);
            int gtok = tokBase + t;
            out[OFF_CODES + (size_t)gtok * NCB + i] = (float)k;
            const float4* cr =
                (const float4*)(codebooks + (size_t)i * 8192 + k * 8);
            float4 ra = __ldg(cr), rb = __ldg(cr + 1);
            float qv[8] = {ra.x, ra.y, ra.z, ra.w, rb.x, rb.y, rb.z, rb.w};
            #pragma unroll
            for (int c = 0; c < 8; c++) {
                float ze = sZe[t * 8 + c];
                float q = qv[c];
                sZq[t * 8 + c] = ze + (q - ze);  // straight-through, fp-faithful
                float df = ze - q;
                lossAcc = fmaf(df, df, lossAcc);
            }
        }
        __syncthreads();

        // ---- out_proj: p = z_q_st @ W_out + out_b; residual -= p ----
        {
            int tl0 = warp * 2;
            float4 qa0 = *(const float4*)&sZq[tl0 * 8];
            float4 qb0 = *(const float4*)&sZq[tl0 * 8 + 4];
            float4 qa1 = *(const float4*)&sZq[(tl0 + 1) * 8];
            float4 qb1 = *(const float4*)&sZq[(tl0 + 1) * 8 + 4];
            #pragma unroll
            for (int j = 0; j < 16; j++) {
                int dim = lane + 32 * j;
                float4 wa = sWout4[2 * dim], wb = sWout4[2 * dim + 1];
                float ob = sOutB[dim];
                float p0 = ob, p1 = ob;
                p0 = fmaf(qa0.x, wa.x, p0); p1 = fmaf(qa1.x, wa.x, p1);
                p0 = fmaf(qa0.y, wa.y, p0); p1 = fmaf(qa1.y, wa.y, p1);
                p0 = fmaf(qa0.z, wa.z, p0); p1 = fmaf(qa1.z, wa.z, p1);
                p0 = fmaf(qa0.w, wa.w, p0); p1 = fmaf(qa1.w, wa.w, p1);
                p0 = fmaf(qb0.x, wb.x, p0); p1 = fmaf(qb1.x, wb.x, p1);
                p0 = fmaf(qb0.y, wb.y, p0); p1 = fmaf(qb1.y, wb.y, p1);
                p0 = fmaf(qb0.z, wb.z, p0); p1 = fmaf(qb1.z, wb.z, p1);
                p0 = fmaf(qb0.w, wb.w, p0); p1 = fmaf(qb1.w, wb.w, p1);
                res0[j] -= p0;
                res1[j] -= p1;
            }
        }
    }

    // ---- z_q = z - residual_final (invariant: z_q + residual == z) ----
    #pragma unroll
    for (int j = 0; j < 16; j++) {
        size_t i0 = (size_t)t0g * DDIM + lane + 32 * j;
        out[i0]        = z[i0]        - res0[j];
        out[i0 + DDIM] = z[i0 + DDIM] - res1[j];
    }

    // ---- loss block-reduce + global accumulate ----
    if (tid < 32) {
        float s = lossAcc;
        #pragma unroll
        for (int off = 16; off >= 1; off >>= 1)
            s += __shfl_xor_sync(0xffffffffu, s, off);
        if (lane == 0) atomicAdd(&g_loss, (double)s);
    }
}

// ------------------------------ launcher ----------------------------------
extern "C" void kernel_launch(void* const* d_in, const int* in_sizes, int n_in,
                              void* d_out, int out_size) {
    const float* z      = (const float*)d_in[0];
    const float* in_v   = (const float*)d_in[1];
    const float* in_g   = (const float*)d_in[2];
    const float* in_b   = (const float*)d_in[3];
    const float* out_v  = (const float*)d_in[4];
    const float* out_g  = (const float*)d_in[5];
    const float* out_b  = (const float*)d_in[6];
    const float* cbooks = (const float*)d_in[7];
    float* out = (float*)d_out;

    cudaFuncSetAttribute(rvq_main, cudaFuncAttributeMaxDynamicSharedMemorySize,
                         SMEM_BYTES);

    rvq_zero<<<1, 1>>>();
    rvq_pre<<<NCB, THREADS>>>(in_v, in_g, out_v, out_g, cbooks);
    rvq_main<<<NBLOCKS, THREADS, SMEM_BYTES>>>(z, in_b, out_b, cbooks, out);
    rvq_fin<<<1, 1>>>(out);
}